// round 15
// baseline (speedup 1.0000x reference)
#include <cuda_runtime.h>
#include <cuda_bf16.h>
#include <math_constants.h>
#include <cstdint>

#define Bn 16
#define Sn 2048
#define Dn 1024
#define Hn 64
#define Mn (Bn * Sn)   // 32768

typedef __nv_bfloat16 bf16;

// ---------------- scratch (device globals; no allocations allowed) ----------
__device__ __align__(16) bf16  g_queryh[(size_t)Mn * Dn], g_queryl[(size_t)Mn * Dn];
__device__ __align__(16) bf16  g_keyh[(size_t)Mn * Dn],   g_keyl[(size_t)Mn * Dn];
__device__ __align__(16) bf16  g_Rh[(size_t)Mn * Dn],     g_Rl[(size_t)Mn * Dn];
__device__ __align__(16) bf16  g_wqh[Dn * Dn], g_wql[Dn * Dn];
__device__ __align__(16) bf16  g_wkh[Dn * Dn], g_wkl[Dn * Dn];
__device__ __align__(16) bf16  g_Ph[Dn * Dn],  g_Pl[Dn * Dn];
__device__ __align__(16) bf16  g_w1th[Hn * Dn], g_w1tl[Hn * Dn];   // w1^T [H,D]
__device__ __align__(16) bf16  g_w2th[Sn * Hn], g_w2tl[Sn * Hn];
__device__ __align__(16) bf16  g_hh[(size_t)Mn * Hn], g_hl[(size_t)Mn * Hn];
__device__ __align__(16) bf16  g_attnh[(size_t)Bn * Sn * Sn], g_attnl[(size_t)Bn * Sn * Sn];
__device__ __align__(16) bf16  g_vth[(size_t)Bn * Dn * Sn],   g_vtl[(size_t)Bn * Dn * Sn];
__device__ __align__(16) float g_logits[(size_t)Bn * Sn * Sn];
__device__ __align__(16) float g_u[Dn], g_v[Dn];
__device__ __align__(16) float g_c[Mn], g_d[Mn];
__device__ __align__(16) float g_bb[4];

// ---------------- helpers -----------------------------------------------------
__device__ __forceinline__ void split_bf16(float x, bf16& hi, bf16& lo) {
    hi = __float2bfloat16_rn(x);
    lo = __float2bfloat16_rn(x - __bfloat162float(hi));
}

__device__ __forceinline__ void ldsm_x4(uint32_t& r0, uint32_t& r1, uint32_t& r2, uint32_t& r3,
                                        const void* p) {
    uint32_t addr = (uint32_t)__cvta_generic_to_shared(p);
    asm volatile("ldmatrix.sync.aligned.m8n8.x4.shared.b16 {%0,%1,%2,%3}, [%4];"
                 : "=r"(r0), "=r"(r1), "=r"(r2), "=r"(r3) : "r"(addr));
}

__device__ __forceinline__ void mma_bf16(float4& d, const uint32_t* a, const uint32_t* b) {
    asm volatile(
        "mma.sync.aligned.m16n8k16.row.col.f32.bf16.bf16.f32 "
        "{%0,%1,%2,%3}, {%4,%5,%6,%7}, {%8,%9}, {%0,%1,%2,%3};"
        : "+f"(d.x), "+f"(d.y), "+f"(d.z), "+f"(d.w)
        : "r"(a[0]), "r"(a[1]), "r"(a[2]), "r"(a[3]), "r"(b[0]), "r"(b[1]));
}

#define CP_ASYNC16(dst_u32, src_ptr)                                            \
    asm volatile("cp.async.cg.shared.global [%0], [%1], 16;"                    \
                 :: "r"(dst_u32), "l"(src_ptr) : "memory")
#define CP_COMMIT()  asm volatile("cp.async.commit_group;" ::: "memory")
#define CP_WAIT0()   asm volatile("cp.async.wait_group 0;" ::: "memory")

// =============================================================================
// bf16 3x-split NT GEMM: C[M,N] = (Ah+Al)[M,K] * ((Bh+Bl)[N,K])^T
// optional: fused phase2 += A2*B2^T ; col bias ; row/col corrections ;
// relu ; N-guard ; output fp32 or split bf16 hi/lo.
// CTA 128x128, warp 64x32, BK=32, double-buffered smem via cp.async,
// ldmatrix + m16n8k16, mi-outer fragment schedule, __launch_bounds__(256,2).
// =============================================================================
#define TSTR 40   // smem row stride in bf16 (80 B: 16B-aligned, conflict-free LDSM)

template <bool PHASE2, bool BIAS, bool SPLITOUT, bool ROWCOL, bool RELU2, bool GUARD>
__global__ void __launch_bounds__(256, 2)
bf16_nt(const bf16* __restrict__ Ah_g, const bf16* __restrict__ Al_g,
        const bf16* __restrict__ Bh_g, const bf16* __restrict__ Bl_g,
        const bf16* __restrict__ A2h,  const bf16* __restrict__ A2l,
        const bf16* __restrict__ B2h,  const bf16* __restrict__ B2l,
        const float* __restrict__ bias,
        const float* __restrict__ rowv, const float* __restrict__ colv,
        float* __restrict__ C, bf16* __restrict__ Ch, bf16* __restrict__ Cl,
        int ldc, int K1, int lda, int ldb, int K2, int lda2, int ldb2,
        long long sA, long long sB, long long sC, long long sA2, int nlim)
{
    Ah_g += (size_t)blockIdx.z * sA;  Al_g += (size_t)blockIdx.z * sA;
    Bh_g += (size_t)blockIdx.z * sB;  Bl_g += (size_t)blockIdx.z * sB;
    if (PHASE2) { A2h += (size_t)blockIdx.z * sA2; A2l += (size_t)blockIdx.z * sA2; }
    if (ROWCOL) { rowv += (size_t)blockIdx.z * Sn; colv += (size_t)blockIdx.z * Sn; }
    const size_t cof = (size_t)blockIdx.z * sC;

    // [buf][mat: 0=Ah 1=Al 2=Bh 3=Bl][row][k]
    __shared__ bf16 sm[2][4][128][TSTR];

    const int tid  = threadIdx.x;
    const int lane = tid & 31;
    const int wid  = tid >> 5;
    const int wm   = (wid & 1) * 64;
    const int wn   = (wid >> 1) * 32;
    const int bm   = blockIdx.y * 128;
    const int bn   = blockIdx.x * 128;

    const int l_row  = tid >> 1;
    const int l_half = (tid & 1) * 16;
    int b_lrow = bn + l_row;
    if (GUARD && b_lrow >= nlim) b_lrow = nlim - 1;

    const uint32_t smb = (uint32_t)__cvta_generic_to_shared(sm)
                       + (uint32_t)(l_row * (TSTR * 2) + l_half * 2);

    const int a_r = lane & 15;
    const int a_c = (lane >> 4) * 8;
    const int b_r = ((lane >> 4) & 1) * 8 + (lane & 7);
    const int b_c = ((lane >> 3) & 1) * 8;

    float4 acc[4][4];
#pragma unroll
    for (int i = 0; i < 4; ++i)
#pragma unroll
        for (int j = 0; j < 4; ++j) acc[i][j] = make_float4(0.f, 0.f, 0.f, 0.f);

    const int nch1 = K1 >> 5;
    const int nch  = nch1 + (PHASE2 ? (K2 >> 5) : 0);

#define FILL(T, BUF)                                                               \
    {                                                                              \
        const int _t = (T);                                                        \
        const bf16 *pa_h, *pa_l, *pb_h, *pb_l;                                     \
        if (!PHASE2 || _t < nch1) {                                                \
            const int k0 = _t * 32 + l_half;                                       \
            pa_h = Ah_g + (size_t)(bm + l_row) * lda + k0;                         \
            pa_l = Al_g + (size_t)(bm + l_row) * lda + k0;                         \
            pb_h = Bh_g + (size_t)b_lrow * ldb + k0;                               \
            pb_l = Bl_g + (size_t)b_lrow * ldb + k0;                               \
        } else {                                                                   \
            const int k0 = (_t - nch1) * 32 + l_half;                              \
            pa_h = A2h + (size_t)(bm + l_row) * lda2 + k0;                         \
            pa_l = A2l + (size_t)(bm + l_row) * lda2 + k0;                         \
            pb_h = B2h + (size_t)b_lrow * ldb2 + k0;                               \
            pb_l = B2l + (size_t)b_lrow * ldb2 + k0;                               \
        }                                                                          \
        const uint32_t d0 = smb + (uint32_t)(BUF) * 40960u;                        \
        CP_ASYNC16(d0,                   pa_h);  CP_ASYNC16(d0 + 16,          pa_h + 8); \
        CP_ASYNC16(d0 + 10240u,          pa_l);  CP_ASYNC16(d0 + 10240u + 16, pa_l + 8); \
        CP_ASYNC16(d0 + 20480u,          pb_h);  CP_ASYNC16(d0 + 20480u + 16, pb_h + 8); \
        CP_ASYNC16(d0 + 30720u,          pb_l);  CP_ASYNC16(d0 + 30720u + 16, pb_l + 8); \
        CP_COMMIT();                                                               \
    }

    FILL(0, 0);
    CP_WAIT0();
    __syncthreads();

    for (int t = 0; t < nch; ++t) {
        const int buf = t & 1;
        const bool more = (t + 1 < nch);
        if (more) FILL(t + 1, buf ^ 1);

#pragma unroll
        for (int kk = 0; kk < 2; ++kk) {
            const int kb = kk * 16;

            uint32_t bh[4][2], bl[4][2];
#pragma unroll
            for (int p = 0; p < 2; ++p) {
                ldsm_x4(bh[2 * p][0], bh[2 * p][1], bh[2 * p + 1][0], bh[2 * p + 1][1],
                        &sm[buf][2][wn + p * 16 + b_r][kb + b_c]);
                ldsm_x4(bl[2 * p][0], bl[2 * p][1], bl[2 * p + 1][0], bl[2 * p + 1][1],
                        &sm[buf][3][wn + p * 16 + b_r][kb + b_c]);
            }

#pragma unroll
            for (int mi = 0; mi < 4; ++mi) {
                uint32_t ah[4], al[4];
                ldsm_x4(ah[0], ah[1], ah[2], ah[3],
                        &sm[buf][0][wm + mi * 16 + a_r][kb + a_c]);
                ldsm_x4(al[0], al[1], al[2], al[3],
                        &sm[buf][1][wm + mi * 16 + a_r][kb + a_c]);
#pragma unroll
                for (int ni = 0; ni < 4; ++ni)
                    mma_bf16(acc[mi][ni], ah, bl[ni]);
#pragma unroll
                for (int ni = 0; ni < 4; ++ni)
                    mma_bf16(acc[mi][ni], al, bh[ni]);
#pragma unroll
                for (int ni = 0; ni < 4; ++ni)
                    mma_bf16(acc[mi][ni], ah, bh[ni]);
            }
        }

        if (more) {
            CP_WAIT0();
            __syncthreads();
        }
    }
#undef FILL

    const int er = lane >> 2;
    const int ec = (lane & 3) * 2;
#pragma unroll
    for (int mi = 0; mi < 4; ++mi) {
        const int row = bm + wm + mi * 16 + er;
        float r0 = 0.f, r1 = 0.f;
        if (ROWCOL) { r0 = rowv[row]; r1 = rowv[row + 8]; }
#pragma unroll
        for (int ni = 0; ni < 4; ++ni) {
            const int col = bn + wn + ni * 8 + ec;
            if (GUARD && col >= nlim) continue;
            float2 v0 = make_float2(acc[mi][ni].x, acc[mi][ni].y);
            float2 v1 = make_float2(acc[mi][ni].z, acc[mi][ni].w);
            if (BIAS) {
                const float2 bi = *(const float2*)(bias + col);
                v0.x += bi.x; v0.y += bi.y;
                v1.x += bi.x; v1.y += bi.y;
            }
            if (ROWCOL) {
                const float2 cv = *(const float2*)(colv + col);
                v0.x += cv.x + r0; v0.y += cv.y + r0;
                v1.x += cv.x + r1; v1.y += cv.y + r1;
            }
            if (RELU2) {
                v0.x = fmaxf(v0.x, 0.f); v0.y = fmaxf(v0.y, 0.f);
                v1.x = fmaxf(v1.x, 0.f); v1.y = fmaxf(v1.y, 0.f);
            }
            if (SPLITOUT) {
                __nv_bfloat162 h2, l2;
                split_bf16(v0.x, h2.x, l2.x);  split_bf16(v0.y, h2.y, l2.y);
                *(__nv_bfloat162*)(Ch + cof + (size_t)row * ldc + col) = h2;
                *(__nv_bfloat162*)(Cl + cof + (size_t)row * ldc + col) = l2;
                split_bf16(v1.x, h2.x, l2.x);  split_bf16(v1.y, h2.y, l2.y);
                *(__nv_bfloat162*)(Ch + cof + (size_t)(row + 8) * ldc + col) = h2;
                *(__nv_bfloat162*)(Cl + cof + (size_t)(row + 8) * ldc + col) = l2;
            } else {
                *(float2*)(C + cof + (size_t)row * ldc + col)       = v0;
                *(float2*)(C + cof + (size_t)(row + 8) * ldc + col) = v1;
            }
        }
    }
}

// ---------------- transpose fp32 -> split bf16 hi/lo -------------------------
__global__ void transpose_split(const float* __restrict__ in,
                                bf16* __restrict__ oh, bf16* __restrict__ ol,
                                int R, int C, long long sIn, long long sOut)
{
    __shared__ float t[32][33];
    in += (size_t)blockIdx.z * sIn;
    oh += (size_t)blockIdx.z * sOut;
    ol += (size_t)blockIdx.z * sOut;
    const int r0 = blockIdx.y * 32, c0 = blockIdx.x * 32;
    const int x = threadIdx.x, y = threadIdx.y;
#pragma unroll
    for (int i = y; i < 32; i += 8)
        if (r0 + i < R && c0 + x < C) t[i][x] = in[(size_t)(r0 + i) * C + c0 + x];
    __syncthreads();
#pragma unroll
    for (int i = y; i < 32; i += 8)
        if (c0 + i < C && r0 + x < R) {
            bf16 hi, lo;
            split_bf16(t[x][i], hi, lo);
            oh[(size_t)(c0 + i) * R + r0 + x] = hi;
            ol[(size_t)(c0 + i) * R + r0 + x] = lo;
        }
}

// ---------------- flat fp32 -> split bf16 hi/lo -------------------------------
__global__ void convert_split(const float* __restrict__ in,
                              bf16* __restrict__ oh, bf16* __restrict__ ol, int n4)
{
    const int i = blockIdx.x * 256 + threadIdx.x;
    if (i < n4) {
        const float4 f = ((const float4*)in)[i];
        __nv_bfloat162 h0, l0, h1, l1;
        split_bf16(f.x, h0.x, l0.x);  split_bf16(f.y, h0.y, l0.y);
        split_bf16(f.z, h1.x, l1.x);  split_bf16(f.w, h1.y, l1.y);
        ((__nv_bfloat162*)oh)[2 * i]     = h0;
        ((__nv_bfloat162*)oh)[2 * i + 1] = h1;
        ((__nv_bfloat162*)ol)[2 * i]     = l0;
        ((__nv_bfloat162*)ol)[2 * i + 1] = l1;
    }
}

// ---------------- convert + fused row-dot: one block per row (cols = Dn) -----
__global__ void __launch_bounds__(256)
convert_split_dot(const float* __restrict__ in,
                  bf16* __restrict__ oh, bf16* __restrict__ ol,
                  const float* __restrict__ vec, float* __restrict__ dotOut,
                  const float* __restrict__ addc)
{
    const size_t row = blockIdx.x;
    const int tid = threadIdx.x;
    const float4 f = ((const float4*)(in + row * Dn))[tid];
    const float4 uu = ((const float4*)vec)[tid];

    float s = f.x * uu.x + f.y * uu.y + f.z * uu.z + f.w * uu.w;

    __nv_bfloat162 h0, l0, h1, l1;
    split_bf16(f.x, h0.x, l0.x);  split_bf16(f.y, h0.y, l0.y);
    split_bf16(f.z, h1.x, l1.x);  split_bf16(f.w, h1.y, l1.y);
    ((__nv_bfloat162*)(oh + row * Dn))[2 * tid]     = h0;
    ((__nv_bfloat162*)(oh + row * Dn))[2 * tid + 1] = h1;
    ((__nv_bfloat162*)(ol + row * Dn))[2 * tid]     = l0;
    ((__nv_bfloat162*)(ol + row * Dn))[2 * tid + 1] = l1;

    __shared__ float sd[8];
#pragma unroll
    for (int o = 16; o; o >>= 1) s += __shfl_xor_sync(0xffffffffu, s, o);
    if ((tid & 31) == 0) sd[tid >> 5] = s;
    __syncthreads();
    if (tid < 32) {
        float x = (tid < 8) ? sd[tid] : 0.f;
#pragma unroll
        for (int o = 4; o; o >>= 1) x += __shfl_xor_sync(0xffffffffu, x, o);
        if (tid == 0) dotOut[row] = x + (addc ? addc[0] : 0.f);
    }
}

// ---------------- small fp32 vector kernels ----------------------------------
__global__ void dot_vec(const float* __restrict__ a, const float* __restrict__ b,
                        float* __restrict__ out, int n)
{
    __shared__ float sd[8];
    float s = 0.f;
    for (int i = threadIdx.x; i < (n >> 2); i += 256) {
        const float4 x = ((const float4*)a)[i], y = ((const float4*)b)[i];
        s += x.x * y.x + x.y * y.y + x.z * y.z + x.w * y.w;
    }
#pragma unroll
    for (int o = 16; o; o >>= 1) s += __shfl_xor_sync(0xffffffffu, s, o);
    if ((threadIdx.x & 31) == 0) sd[threadIdx.x >> 5] = s;
    __syncthreads();
    if (threadIdx.x < 32) {
        float x = (threadIdx.x < 8) ? sd[threadIdx.x] : 0.f;
#pragma unroll
        for (int o = 4; o; o >>= 1) x += __shfl_xor_sync(0xffffffffu, x, o);
        if (threadIdx.x == 0) out[0] = x;
    }
}

__global__ void gemv_rows(const float* __restrict__ Mt, const float* __restrict__ x,
                          float* __restrict__ y, int C, const float* __restrict__ addc)
{
    const int row = blockIdx.x * 8 + threadIdx.y;
    const float* rp = Mt + (size_t)row * C;
    float s = 0.f;
    for (int j = threadIdx.x; j < (C >> 2); j += 32) {
        const float4 a = ((const float4*)rp)[j];
        const float4 b = ((const float4*)x)[j];
        s += a.x * b.x + a.y * b.y + a.z * b.z + a.w * b.w;
    }
#pragma unroll
    for (int o = 16; o; o >>= 1) s += __shfl_xor_sync(0xffffffffu, s, o);
    if (threadIdx.x == 0) y[row] = s + (addc ? addc[0] : 0.f);
}

// ---------------- row softmax: fp32 out + split bf16 out ----------------------
__global__ void __launch_bounds__(256)
softmax_kernel(const float* __restrict__ logits, float* __restrict__ dst,
               bf16* __restrict__ dh, bf16* __restrict__ dl)
{
    const size_t row = blockIdx.x;
    const float* rp = logits + row * Sn;
    const int tid = threadIdx.x;

    __shared__ float sd[8];

    float v[8];
    float mx = -CUDART_INF_F;
#pragma unroll
    for (int j = 0; j < 8; ++j) {
        v[j] = rp[tid + 256 * j];
        mx = fmaxf(mx, v[j]);
    }
#pragma unroll
    for (int o = 16; o; o >>= 1) mx = fmaxf(mx, __shfl_xor_sync(0xffffffffu, mx, o));
    if ((tid & 31) == 0) sd[tid >> 5] = mx;
    __syncthreads();
    if (tid < 32) {
        float x = (tid < 8) ? sd[tid] : -CUDART_INF_F;
#pragma unroll
        for (int o = 4; o; o >>= 1) x = fmaxf(x, __shfl_xor_sync(0xffffffffu, x, o));
        if (tid == 0) sd[0] = x;
    }
    __syncthreads();
    mx = sd[0];
    __syncthreads();

    float s = 0.f;
#pragma unroll
    for (int j = 0; j < 8; ++j) {
        v[j] = __expf(v[j] - mx);
        s += v[j];
    }
#pragma unroll
    for (int o = 16; o; o >>= 1) s += __shfl_xor_sync(0xffffffffu, s, o);
    if ((tid & 31) == 0) sd[tid >> 5] = s;
    __syncthreads();
    if (tid < 32) {
        float x = (tid < 8) ? sd[tid] : 0.f;
#pragma unroll
        for (int o = 4; o; o >>= 1) x += __shfl_xor_sync(0xffffffffu, x, o);
        if (tid == 0) sd[0] = x;
    }
    __syncthreads();
    const float inv = 1.f / sd[0];

#pragma unroll
    for (int j = 0; j < 8; ++j) {
        const float a = v[j] * inv;
        const size_t o = row * Sn + tid + 256 * j;
        dst[o] = a;
        bf16 hi, lo;
        split_bf16(a, hi, lo);
        dh[o] = hi;
        dl[o] = lo;
    }
}

// ---------------- launch --------------------------------------------------------
extern "C" void kernel_launch(void* const* d_in, const int* in_sizes, int n_in,
                              void* d_out_v, int out_size)
{
    (void)in_sizes; (void)n_in;
    const float* query = (const float*)d_in[0];
    const float* key   = (const float*)d_in[1];
    const float* value = (const float*)d_in[2];
    const float* w1    = (const float*)d_in[3];
    const float* b1    = (const float*)d_in[4];
    const float* w2    = (const float*)d_in[5];
    const float* b2    = (const float*)d_in[6];
    const float* wq    = (const float*)d_in[7];
    const float* bq    = (const float*)d_in[8];
    const float* wk    = (const float*)d_in[9];
    const float* bk    = (const float*)d_in[10];
    float* d_out = (float*)d_out_v;

    // streams + events (created once on the non-captured correctness call)
    static cudaStream_t s1 = nullptr, s2 = nullptr, s3 = nullptr;
    static cudaEvent_t evFork = nullptr, evSide = nullptr, evKey = nullptr;
    static cudaEvent_t evL0 = nullptr, evL1 = nullptr, evEnd = nullptr;
    if (s1 == nullptr) {
        cudaStreamCreateWithFlags(&s1, cudaStreamNonBlocking);
        cudaStreamCreateWithFlags(&s2, cudaStreamNonBlocking);
        cudaStreamCreateWithFlags(&s3, cudaStreamNonBlocking);
        cudaEventCreateWithFlags(&evFork, cudaEventDisableTiming);
        cudaEventCreateWithFlags(&evSide, cudaEventDisableTiming);
        cudaEventCreateWithFlags(&evKey,  cudaEventDisableTiming);
        cudaEventCreateWithFlags(&evL0,   cudaEventDisableTiming);
        cudaEventCreateWithFlags(&evL1,   cudaEventDisableTiming);
        cudaEventCreateWithFlags(&evEnd,  cudaEventDisableTiming);
    }

#define SYM(var, sym) cudaGetSymbolAddress((void**)&var, sym)
    bf16 *queryh, *queryl, *keyh, *keyl, *Rh, *Rl;
    bf16 *wqh, *wql, *wkh, *wkl, *Ph, *Pl, *w1th, *w1tl, *w2th, *w2tl, *hh, *hl;
    bf16 *attnh, *attnl, *vth, *vtl;
    float *logits, *u, *v, *cvec, *dvec, *bb;
    SYM(queryh, g_queryh); SYM(queryl, g_queryl);
    SYM(keyh, g_keyh);     SYM(keyl, g_keyl);
    SYM(Rh, g_Rh); SYM(Rl, g_Rl);
    SYM(wqh, g_wqh); SYM(wql, g_wql);
    SYM(wkh, g_wkh); SYM(wkl, g_wkl);
    SYM(Ph, g_Ph); SYM(Pl, g_Pl);
    SYM(w1th, g_w1th); SYM(w1tl, g_w1tl);
    SYM(w2th, g_w2th); SYM(w2tl, g_w2tl);
    SYM(hh, g_hh); SYM(hl, g_hl);
    SYM(attnh, g_attnh); SYM(attnl, g_attnl);
    SYM(vth, g_vth); SYM(vtl, g_vtl);
    SYM(logits, g_logits);
    SYM(u, g_u); SYM(v, g_v); SYM(cvec, g_c); SYM(dvec, g_d); SYM(bb, g_bb);
#undef SYM

    const long long BSD = (long long)Bn * Sn * Dn;
    const long long BSS = (long long)Bn * Sn * Sn;

    float* out_ptr  = nullptr;
    float* attn_ptr = nullptr;
    if ((long long)out_size == BSD + BSS) { out_ptr = d_out; attn_ptr = d_out + BSD; }
    else if ((long long)out_size == BSS)  { attn_ptr = d_out; }
    else                                  { out_ptr = d_out; }

    const int BIGN = 1 << 30;
    float* attn_final = attn_ptr ? attn_ptr : logits;

    // ---- main: bias pre-vectors; fork ----
    dot_vec<<<1, 256>>>(bq, bk, bb, Dn);
    gemv_rows<<<Dn / 8, dim3(32, 8)>>>(wq, bk, u, Dn, nullptr);
    gemv_rows<<<Dn / 8, dim3(32, 8)>>>(wk, bq, v, Dn, nullptr);
    cudaEventRecord(evFork, 0);

    // ---- s1: query chain (query conv, transposes, h) ----
    cudaStreamWaitEvent(s1, evFork, 0);
    convert_split_dot<<<Mn, 256, 0, s1>>>(query, queryh, queryl, u, cvec, bb);
    transpose_split<<<dim3(Hn / 32, Dn / 32, 1), dim3(32, 8), 0, s1>>>(
        w1, w1th, w1tl, Dn, Hn, 0, 0);
    transpose_split<<<dim3(Sn / 32, 2, 1), dim3(32, 8), 0, s1>>>(
        w2, w2th, w2tl, Hn, Sn, 0, 0);
    transpose_split<<<dim3(Dn / 32, Sn / 32, Bn), dim3(32, 8), 0, s1>>>(
        value, vth, vtl, Sn, Dn, (long long)Sn * Dn, (long long)Sn * Dn);
    bf16_nt<false, true, true, false, true, true><<<dim3(1, Mn / 128, 1), 256, 0, s1>>>(
        queryh, queryl, w1th, w1tl, nullptr, nullptr, nullptr, nullptr,
        b1, nullptr, nullptr, nullptr, hh, hl,
        Hn, Dn, Dn, Dn, 0, 0, 0, 0, 0, 0, 0, Hn);
    cudaEventRecord(evSide, s1);

    // ---- s2: key convert (only feeds R) ----
    cudaStreamWaitEvent(s2, evFork, 0);
    convert_split_dot<<<Mn, 256, 0, s2>>>(key, keyh, keyl, v, dvec, nullptr);
    cudaEventRecord(evKey, s2);

    // ---- main: wq/wk converts + P (concurrent with s1, s2) ----
    convert_split<<<(Dn * (Dn / 4) + 255) / 256, 256>>>(wq, wqh, wql, Dn * (Dn / 4));
    convert_split<<<(Dn * (Dn / 4) + 255) / 256, 256>>>(wk, wkh, wkl, Dn * (Dn / 4));
    bf16_nt<false, false, true, false, false, false><<<dim3(Dn / 128, Dn / 128, 1), 256>>>(
        wqh, wql, wkh, wkl, nullptr, nullptr, nullptr, nullptr,
        nullptr, nullptr, nullptr, nullptr, Ph, Pl,
        Dn, Dn, Dn, Dn, 0, 0, 0, 0, 0, 0, 0, BIGN);

    // ---- main: R = key @ P^T (needs keyh) ----
    cudaStreamWaitEvent(0, evKey, 0);
    bf16_nt<false, false, true, false, false, false><<<dim3(Dn / 128, Mn / 128, 1), 256>>>(
        keyh, keyl, Ph, Pl, nullptr, nullptr, nullptr, nullptr,
        nullptr, nullptr, nullptr, nullptr, Rh, Rl,
        Dn, Dn, Dn, Dn, 0, 0, 0, 0, 0, 0, 0, BIGN);

    // ---- join side chain, then logits (+ pipelined softmax / AV) ----
    cudaStreamWaitEvent(0, evSide, 0);

    const long long sSD = (long long)Sn * Dn;
    const long long sSS = (long long)Sn * Sn;
    const long long sDS = (long long)Dn * Sn;
    const long long sSH = (long long)Sn * Hn;

    if (out_ptr) {
        const int HB = Bn / 2;   // 8 batches per half
        // logits half 0
        bf16_nt<true, true, false, true, false, false><<<dim3(Sn / 128, Sn / 128, HB), 256>>>(
            queryh, queryl, Rh, Rl, hh, hl, w2th, w2tl,
            b2, cvec, dvec, logits, nullptr, nullptr,
            Sn, Dn, Dn, Dn, Hn, Hn, Hn, sSD, sSD, sSS, sSH, BIGN);
        cudaEventRecord(evL0, 0);
        // logits half 1 (runs concurrently with s3's softmax/AV of half 0)
        const size_t o1SD = (size_t)HB * sSD, o1SS = (size_t)HB * sSS;
        const size_t o1SH = (size_t)HB * sSH, o1S = (size_t)HB * Sn;
        bf16_nt<true, true, false, true, false, false><<<dim3(Sn / 128, Sn / 128, HB), 256>>>(
            queryh + o1SD, queryl + o1SD, Rh + o1SD, Rl + o1SD,
            hh + o1SH, hl + o1SH, w2th, w2tl,
            b2, cvec + o1S, dvec + o1S, logits + o1SS, nullptr, nullptr,
            Sn, Dn, Dn, Dn, Hn, Hn, Hn, sSD, sSD, sSS, sSH, BIGN);
        cudaEventRecord(evL1, 0);

        // s3: softmax + AV per half
        const size_t o1DS = (size_t)HB * sDS;
        cudaStreamWaitEvent(s3, evL0, 0);
        softmax_kernel<<<HB * Sn, 256, 0, s3>>>(logits, attn_final, attnh, attnl);
        bf16_nt<false, false, false, false, false, false><<<dim3(Dn / 128, Sn / 128, HB), 256, 0, s3>>>(
            attnh, attnl, vth, vtl, nullptr, nullptr, nullptr, nullptr,
            nullptr, nullptr, nullptr, out_ptr, nullptr, nullptr,
            Dn, Sn, Sn, Sn, 0, 0, 0, sSS, sDS, sSD, 0, BIGN);
        cudaStreamWaitEvent(s3, evL1, 0);
        softmax_kernel<<<HB * Sn, 256, 0, s3>>>(logits + o1SS, attn_final + o1SS,
                                                attnh + o1SS, attnl + o1SS);
        bf16_nt<false, false, false, false, false, false><<<dim3(Dn / 128, Sn / 128, HB), 256, 0, s3>>>(
            attnh + o1SS, attnl + o1SS, vth + o1DS, vtl + o1DS,
            nullptr, nullptr, nullptr, nullptr,
            nullptr, nullptr, nullptr, out_ptr + o1SD, nullptr, nullptr,
            Dn, Sn, Sn, Sn, 0, 0, 0, sSS, sDS, sSD, 0, BIGN);
        cudaEventRecord(evEnd, s3);
        cudaStreamWaitEvent(0, evEnd, 0);
    } else {
        bf16_nt<true, true, false, true, false, false><<<dim3(Sn / 128, Sn / 128, Bn), 256>>>(
            queryh, queryl, Rh, Rl, hh, hl, w2th, w2tl,
            b2, cvec, dvec, logits, nullptr, nullptr,
            Sn, Dn, Dn, Dn, Hn, Hn, Hn, sSD, sSD, sSS, sSH, BIGN);
        softmax_kernel<<<Bn * Sn, 256>>>(logits, attn_final, attnh, attnl);
    }
}

// round 16
// speedup vs baseline: 1.0074x; 1.0074x over previous
#include <cuda_runtime.h>
#include <cuda_bf16.h>
#include <math_constants.h>
#include <cstdint>

#define Bn 16
#define Sn 2048
#define Dn 1024
#define Hn 64
#define Mn (Bn * Sn)   // 32768

typedef __nv_bfloat16 bf16;

// ---------------- scratch (device globals; no allocations allowed) ----------
__device__ __align__(16) bf16  g_queryh[(size_t)Mn * Dn], g_queryl[(size_t)Mn * Dn];
__device__ __align__(16) bf16  g_keyh[(size_t)Mn * Dn],   g_keyl[(size_t)Mn * Dn];
__device__ __align__(16) bf16  g_Rh[(size_t)Mn * Dn],     g_Rl[(size_t)Mn * Dn];
__device__ __align__(16) bf16  g_wqh[Dn * Dn], g_wql[Dn * Dn];
__device__ __align__(16) bf16  g_wkh[Dn * Dn], g_wkl[Dn * Dn];
__device__ __align__(16) bf16  g_Ph[Dn * Dn],  g_Pl[Dn * Dn];
__device__ __align__(16) bf16  g_w1th[Hn * Dn], g_w1tl[Hn * Dn];   // w1^T [H,D]
__device__ __align__(16) bf16  g_w2th[Sn * Hn], g_w2tl[Sn * Hn];
__device__ __align__(16) bf16  g_hh[(size_t)Mn * Hn], g_hl[(size_t)Mn * Hn];
__device__ __align__(16) bf16  g_attnh[(size_t)Bn * Sn * Sn], g_attnl[(size_t)Bn * Sn * Sn];
__device__ __align__(16) bf16  g_vth[(size_t)Bn * Dn * Sn],   g_vtl[(size_t)Bn * Dn * Sn];
__device__ __align__(16) float g_logits[(size_t)Bn * Sn * Sn];
__device__ __align__(16) float g_u[Dn], g_v[Dn];
__device__ __align__(16) float g_c[Mn], g_d[Mn];
__device__ __align__(16) float g_bb[4];

// ---------------- helpers -----------------------------------------------------
__device__ __forceinline__ void split_bf16(float x, bf16& hi, bf16& lo) {
    hi = __float2bfloat16_rn(x);
    lo = __float2bfloat16_rn(x - __bfloat162float(hi));
}

__device__ __forceinline__ void ldsm_x4(uint32_t& r0, uint32_t& r1, uint32_t& r2, uint32_t& r3,
                                        const void* p) {
    uint32_t addr = (uint32_t)__cvta_generic_to_shared(p);
    asm volatile("ldmatrix.sync.aligned.m8n8.x4.shared.b16 {%0,%1,%2,%3}, [%4];"
                 : "=r"(r0), "=r"(r1), "=r"(r2), "=r"(r3) : "r"(addr));
}

__device__ __forceinline__ void mma_bf16(float4& d, const uint32_t* a, const uint32_t* b) {
    asm volatile(
        "mma.sync.aligned.m16n8k16.row.col.f32.bf16.bf16.f32 "
        "{%0,%1,%2,%3}, {%4,%5,%6,%7}, {%8,%9}, {%0,%1,%2,%3};"
        : "+f"(d.x), "+f"(d.y), "+f"(d.z), "+f"(d.w)
        : "r"(a[0]), "r"(a[1]), "r"(a[2]), "r"(a[3]), "r"(b[0]), "r"(b[1]));
}

#define CP_ASYNC16(dst_u32, src_ptr)                                            \
    asm volatile("cp.async.cg.shared.global [%0], [%1], 16;"                    \
                 :: "r"(dst_u32), "l"(src_ptr) : "memory")
#define CP_COMMIT()  asm volatile("cp.async.commit_group;" ::: "memory")
#define CP_WAIT0()   asm volatile("cp.async.wait_group 0;" ::: "memory")

// =============================================================================
// bf16 3x-split NT GEMM: C[M,N] = (Ah+Al)[M,K] * ((Bh+Bl)[N,K])^T
// optional: fused phase2 += A2*B2^T ; col bias ; row/col corrections ;
// relu ; N-guard ; output fp32 or split bf16 hi/lo.
// CTA 128x128, warp 64x32, BK=32, double-buffered smem via cp.async,
// ldmatrix + m16n8k16, mi-outer fragment schedule, __launch_bounds__(256,2).
// =============================================================================
#define TSTR 40   // smem row stride in bf16 (80 B: 16B-aligned, conflict-free LDSM)

template <bool PHASE2, bool BIAS, bool SPLITOUT, bool ROWCOL, bool RELU2, bool GUARD>
__global__ void __launch_bounds__(256, 2)
bf16_nt(const bf16* __restrict__ Ah_g, const bf16* __restrict__ Al_g,
        const bf16* __restrict__ Bh_g, const bf16* __restrict__ Bl_g,
        const bf16* __restrict__ A2h,  const bf16* __restrict__ A2l,
        const bf16* __restrict__ B2h,  const bf16* __restrict__ B2l,
        const float* __restrict__ bias,
        const float* __restrict__ rowv, const float* __restrict__ colv,
        float* __restrict__ C, bf16* __restrict__ Ch, bf16* __restrict__ Cl,
        int ldc, int K1, int lda, int ldb, int K2, int lda2, int ldb2,
        long long sA, long long sB, long long sC, long long sA2, int nlim)
{
    Ah_g += (size_t)blockIdx.z * sA;  Al_g += (size_t)blockIdx.z * sA;
    Bh_g += (size_t)blockIdx.z * sB;  Bl_g += (size_t)blockIdx.z * sB;
    if (PHASE2) { A2h += (size_t)blockIdx.z * sA2; A2l += (size_t)blockIdx.z * sA2; }
    if (ROWCOL) { rowv += (size_t)blockIdx.z * Sn; colv += (size_t)blockIdx.z * Sn; }
    const size_t cof = (size_t)blockIdx.z * sC;

    // [buf][mat: 0=Ah 1=Al 2=Bh 3=Bl][row][k]
    __shared__ bf16 sm[2][4][128][TSTR];

    const int tid  = threadIdx.x;
    const int lane = tid & 31;
    const int wid  = tid >> 5;
    const int wm   = (wid & 1) * 64;
    const int wn   = (wid >> 1) * 32;
    const int bm   = blockIdx.y * 128;
    const int bn   = blockIdx.x * 128;

    const int l_row  = tid >> 1;
    const int l_half = (tid & 1) * 16;
    int b_lrow = bn + l_row;
    if (GUARD && b_lrow >= nlim) b_lrow = nlim - 1;

    const uint32_t smb = (uint32_t)__cvta_generic_to_shared(sm)
                       + (uint32_t)(l_row * (TSTR * 2) + l_half * 2);

    const int a_r = lane & 15;
    const int a_c = (lane >> 4) * 8;
    const int b_r = ((lane >> 4) & 1) * 8 + (lane & 7);
    const int b_c = ((lane >> 3) & 1) * 8;

    float4 acc[4][4];
#pragma unroll
    for (int i = 0; i < 4; ++i)
#pragma unroll
        for (int j = 0; j < 4; ++j) acc[i][j] = make_float4(0.f, 0.f, 0.f, 0.f);

    const int nch1 = K1 >> 5;
    const int nch  = nch1 + (PHASE2 ? (K2 >> 5) : 0);

#define FILL(T, BUF)                                                               \
    {                                                                              \
        const int _t = (T);                                                        \
        const bf16 *pa_h, *pa_l, *pb_h, *pb_l;                                     \
        if (!PHASE2 || _t < nch1) {                                                \
            const int k0 = _t * 32 + l_half;                                       \
            pa_h = Ah_g + (size_t)(bm + l_row) * lda + k0;                         \
            pa_l = Al_g + (size_t)(bm + l_row) * lda + k0;                         \
            pb_h = Bh_g + (size_t)b_lrow * ldb + k0;                               \
            pb_l = Bl_g + (size_t)b_lrow * ldb + k0;                               \
        } else {                                                                   \
            const int k0 = (_t - nch1) * 32 + l_half;                              \
            pa_h = A2h + (size_t)(bm + l_row) * lda2 + k0;                         \
            pa_l = A2l + (size_t)(bm + l_row) * lda2 + k0;                         \
            pb_h = B2h + (size_t)b_lrow * ldb2 + k0;                               \
            pb_l = B2l + (size_t)b_lrow * ldb2 + k0;                               \
        }                                                                          \
        const uint32_t d0 = smb + (uint32_t)(BUF) * 40960u;                        \
        CP_ASYNC16(d0,                   pa_h);  CP_ASYNC16(d0 + 16,          pa_h + 8); \
        CP_ASYNC16(d0 + 10240u,          pa_l);  CP_ASYNC16(d0 + 10240u + 16, pa_l + 8); \
        CP_ASYNC16(d0 + 20480u,          pb_h);  CP_ASYNC16(d0 + 20480u + 16, pb_h + 8); \
        CP_ASYNC16(d0 + 30720u,          pb_l);  CP_ASYNC16(d0 + 30720u + 16, pb_l + 8); \
        CP_COMMIT();                                                               \
    }

    FILL(0, 0);
    CP_WAIT0();
    __syncthreads();

    for (int t = 0; t < nch; ++t) {
        const int buf = t & 1;
        const bool more = (t + 1 < nch);
        if (more) FILL(t + 1, buf ^ 1);

#pragma unroll
        for (int kk = 0; kk < 2; ++kk) {
            const int kb = kk * 16;

            uint32_t bh[4][2], bl[4][2];
#pragma unroll
            for (int p = 0; p < 2; ++p) {
                ldsm_x4(bh[2 * p][0], bh[2 * p][1], bh[2 * p + 1][0], bh[2 * p + 1][1],
                        &sm[buf][2][wn + p * 16 + b_r][kb + b_c]);
                ldsm_x4(bl[2 * p][0], bl[2 * p][1], bl[2 * p + 1][0], bl[2 * p + 1][1],
                        &sm[buf][3][wn + p * 16 + b_r][kb + b_c]);
            }

#pragma unroll
            for (int mi = 0; mi < 4; ++mi) {
                uint32_t ah[4], al[4];
                ldsm_x4(ah[0], ah[1], ah[2], ah[3],
                        &sm[buf][0][wm + mi * 16 + a_r][kb + a_c]);
                ldsm_x4(al[0], al[1], al[2], al[3],
                        &sm[buf][1][wm + mi * 16 + a_r][kb + a_c]);
#pragma unroll
                for (int ni = 0; ni < 4; ++ni)
                    mma_bf16(acc[mi][ni], ah, bl[ni]);
#pragma unroll
                for (int ni = 0; ni < 4; ++ni)
                    mma_bf16(acc[mi][ni], al, bh[ni]);
#pragma unroll
                for (int ni = 0; ni < 4; ++ni)
                    mma_bf16(acc[mi][ni], ah, bh[ni]);
            }
        }

        if (more) {
            CP_WAIT0();
            __syncthreads();
        }
    }
#undef FILL

    const int er = lane >> 2;
    const int ec = (lane & 3) * 2;
#pragma unroll
    for (int mi = 0; mi < 4; ++mi) {
        const int row = bm + wm + mi * 16 + er;
        float r0 = 0.f, r1 = 0.f;
        if (ROWCOL) { r0 = rowv[row]; r1 = rowv[row + 8]; }
#pragma unroll
        for (int ni = 0; ni < 4; ++ni) {
            const int col = bn + wn + ni * 8 + ec;
            if (GUARD && col >= nlim) continue;
            float2 v0 = make_float2(acc[mi][ni].x, acc[mi][ni].y);
            float2 v1 = make_float2(acc[mi][ni].z, acc[mi][ni].w);
            if (BIAS) {
                const float2 bi = *(const float2*)(bias + col);
                v0.x += bi.x; v0.y += bi.y;
                v1.x += bi.x; v1.y += bi.y;
            }
            if (ROWCOL) {
                const float2 cv = *(const float2*)(colv + col);
                v0.x += cv.x + r0; v0.y += cv.y + r0;
                v1.x += cv.x + r1; v1.y += cv.y + r1;
            }
            if (RELU2) {
                v0.x = fmaxf(v0.x, 0.f); v0.y = fmaxf(v0.y, 0.f);
                v1.x = fmaxf(v1.x, 0.f); v1.y = fmaxf(v1.y, 0.f);
            }
            if (SPLITOUT) {
                __nv_bfloat162 h2, l2;
                split_bf16(v0.x, h2.x, l2.x);  split_bf16(v0.y, h2.y, l2.y);
                *(__nv_bfloat162*)(Ch + cof + (size_t)row * ldc + col) = h2;
                *(__nv_bfloat162*)(Cl + cof + (size_t)row * ldc + col) = l2;
                split_bf16(v1.x, h2.x, l2.x);  split_bf16(v1.y, h2.y, l2.y);
                *(__nv_bfloat162*)(Ch + cof + (size_t)(row + 8) * ldc + col) = h2;
                *(__nv_bfloat162*)(Cl + cof + (size_t)(row + 8) * ldc + col) = l2;
            } else {
                *(float2*)(C + cof + (size_t)row * ldc + col)       = v0;
                *(float2*)(C + cof + (size_t)(row + 8) * ldc + col) = v1;
            }
        }
    }
}

// ---------------- transpose fp32 -> split bf16 hi/lo -------------------------
__global__ void transpose_split(const float* __restrict__ in,
                                bf16* __restrict__ oh, bf16* __restrict__ ol,
                                int R, int C, long long sIn, long long sOut)
{
    __shared__ float t[32][33];
    in += (size_t)blockIdx.z * sIn;
    oh += (size_t)blockIdx.z * sOut;
    ol += (size_t)blockIdx.z * sOut;
    const int r0 = blockIdx.y * 32, c0 = blockIdx.x * 32;
    const int x = threadIdx.x, y = threadIdx.y;
#pragma unroll
    for (int i = y; i < 32; i += 8)
        if (r0 + i < R && c0 + x < C) t[i][x] = in[(size_t)(r0 + i) * C + c0 + x];
    __syncthreads();
#pragma unroll
    for (int i = y; i < 32; i += 8)
        if (c0 + i < C && r0 + x < R) {
            bf16 hi, lo;
            split_bf16(t[x][i], hi, lo);
            oh[(size_t)(c0 + i) * R + r0 + x] = hi;
            ol[(size_t)(c0 + i) * R + r0 + x] = lo;
        }
}

// ---------------- flat fp32 -> split bf16 hi/lo -------------------------------
__global__ void convert_split(const float* __restrict__ in,
                              bf16* __restrict__ oh, bf16* __restrict__ ol, int n4)
{
    const int i = blockIdx.x * 256 + threadIdx.x;
    if (i < n4) {
        const float4 f = ((const float4*)in)[i];
        __nv_bfloat162 h0, l0, h1, l1;
        split_bf16(f.x, h0.x, l0.x);  split_bf16(f.y, h0.y, l0.y);
        split_bf16(f.z, h1.x, l1.x);  split_bf16(f.w, h1.y, l1.y);
        ((__nv_bfloat162*)oh)[2 * i]     = h0;
        ((__nv_bfloat162*)oh)[2 * i + 1] = h1;
        ((__nv_bfloat162*)ol)[2 * i]     = l0;
        ((__nv_bfloat162*)ol)[2 * i + 1] = l1;
    }
}

// ---------------- convert + fused row-dot: one block per row (cols = Dn) -----
__global__ void __launch_bounds__(256)
convert_split_dot(const float* __restrict__ in,
                  bf16* __restrict__ oh, bf16* __restrict__ ol,
                  const float* __restrict__ vec, float* __restrict__ dotOut,
                  const float* __restrict__ addc)
{
    const size_t row = blockIdx.x;
    const int tid = threadIdx.x;
    const float4 f = ((const float4*)(in + row * Dn))[tid];
    const float4 uu = ((const float4*)vec)[tid];

    float s = f.x * uu.x + f.y * uu.y + f.z * uu.z + f.w * uu.w;

    __nv_bfloat162 h0, l0, h1, l1;
    split_bf16(f.x, h0.x, l0.x);  split_bf16(f.y, h0.y, l0.y);
    split_bf16(f.z, h1.x, l1.x);  split_bf16(f.w, h1.y, l1.y);
    ((__nv_bfloat162*)(oh + row * Dn))[2 * tid]     = h0;
    ((__nv_bfloat162*)(oh + row * Dn))[2 * tid + 1] = h1;
    ((__nv_bfloat162*)(ol + row * Dn))[2 * tid]     = l0;
    ((__nv_bfloat162*)(ol + row * Dn))[2 * tid + 1] = l1;

    __shared__ float sd[8];
#pragma unroll
    for (int o = 16; o; o >>= 1) s += __shfl_xor_sync(0xffffffffu, s, o);
    if ((tid & 31) == 0) sd[tid >> 5] = s;
    __syncthreads();
    if (tid < 32) {
        float x = (tid < 8) ? sd[tid] : 0.f;
#pragma unroll
        for (int o = 4; o; o >>= 1) x += __shfl_xor_sync(0xffffffffu, x, o);
        if (tid == 0) dotOut[row] = x + (addc ? addc[0] : 0.f);
    }
}

// ---------------- small fp32 vector kernels ----------------------------------
__global__ void dot_vec(const float* __restrict__ a, const float* __restrict__ b,
                        float* __restrict__ out, int n)
{
    __shared__ float sd[8];
    float s = 0.f;
    for (int i = threadIdx.x; i < (n >> 2); i += 256) {
        const float4 x = ((const float4*)a)[i], y = ((const float4*)b)[i];
        s += x.x * y.x + x.y * y.y + x.z * y.z + x.w * y.w;
    }
#pragma unroll
    for (int o = 16; o; o >>= 1) s += __shfl_xor_sync(0xffffffffu, s, o);
    if ((threadIdx.x & 31) == 0) sd[threadIdx.x >> 5] = s;
    __syncthreads();
    if (threadIdx.x < 32) {
        float x = (threadIdx.x < 8) ? sd[threadIdx.x] : 0.f;
#pragma unroll
        for (int o = 4; o; o >>= 1) x += __shfl_xor_sync(0xffffffffu, x, o);
        if (threadIdx.x == 0) out[0] = x;
    }
}

__global__ void gemv_rows(const float* __restrict__ Mt, const float* __restrict__ x,
                          float* __restrict__ y, int C, const float* __restrict__ addc)
{
    const int row = blockIdx.x * 8 + threadIdx.y;
    const float* rp = Mt + (size_t)row * C;
    float s = 0.f;
    for (int j = threadIdx.x; j < (C >> 2); j += 32) {
        const float4 a = ((const float4*)rp)[j];
        const float4 b = ((const float4*)x)[j];
        s += a.x * b.x + a.y * b.y + a.z * b.z + a.w * b.w;
    }
#pragma unroll
    for (int o = 16; o; o >>= 1) s += __shfl_xor_sync(0xffffffffu, s, o);
    if (threadIdx.x == 0) y[row] = s + (addc ? addc[0] : 0.f);
}

// ---------------- row softmax: fp32 out + split bf16 out ----------------------
__global__ void __launch_bounds__(256)
softmax_kernel(const float* __restrict__ logits, float* __restrict__ dst,
               bf16* __restrict__ dh, bf16* __restrict__ dl)
{
    const size_t row = blockIdx.x;
    const float* rp = logits + row * Sn;
    const int tid = threadIdx.x;

    __shared__ float sd[8];

    float v[8];
    float mx = -CUDART_INF_F;
#pragma unroll
    for (int j = 0; j < 8; ++j) {
        v[j] = rp[tid + 256 * j];
        mx = fmaxf(mx, v[j]);
    }
#pragma unroll
    for (int o = 16; o; o >>= 1) mx = fmaxf(mx, __shfl_xor_sync(0xffffffffu, mx, o));
    if ((tid & 31) == 0) sd[tid >> 5] = mx;
    __syncthreads();
    if (tid < 32) {
        float x = (tid < 8) ? sd[tid] : -CUDART_INF_F;
#pragma unroll
        for (int o = 4; o; o >>= 1) x = fmaxf(x, __shfl_xor_sync(0xffffffffu, x, o));
        if (tid == 0) sd[0] = x;
    }
    __syncthreads();
    mx = sd[0];
    __syncthreads();

    float s = 0.f;
#pragma unroll
    for (int j = 0; j < 8; ++j) {
        v[j] = __expf(v[j] - mx);
        s += v[j];
    }
#pragma unroll
    for (int o = 16; o; o >>= 1) s += __shfl_xor_sync(0xffffffffu, s, o);
    if ((tid & 31) == 0) sd[tid >> 5] = s;
    __syncthreads();
    if (tid < 32) {
        float x = (tid < 8) ? sd[tid] : 0.f;
#pragma unroll
        for (int o = 4; o; o >>= 1) x += __shfl_xor_sync(0xffffffffu, x, o);
        if (tid == 0) sd[0] = x;
    }
    __syncthreads();
    const float inv = 1.f / sd[0];

#pragma unroll
    for (int j = 0; j < 8; ++j) {
        const float a = v[j] * inv;
        const size_t o = row * Sn + tid + 256 * j;
        dst[o] = a;
        bf16 hi, lo;
        split_bf16(a, hi, lo);
        dh[o] = hi;
        dl[o] = lo;
    }
}

// ---------------- launch --------------------------------------------------------
extern "C" void kernel_launch(void* const* d_in, const int* in_sizes, int n_in,
                              void* d_out_v, int out_size)
{
    (void)in_sizes; (void)n_in;
    const float* query = (const float*)d_in[0];
    const float* key   = (const float*)d_in[1];
    const float* value = (const float*)d_in[2];
    const float* w1    = (const float*)d_in[3];
    const float* b1    = (const float*)d_in[4];
    const float* w2    = (const float*)d_in[5];
    const float* b2    = (const float*)d_in[6];
    const float* wq    = (const float*)d_in[7];
    const float* bq    = (const float*)d_in[8];
    const float* wk    = (const float*)d_in[9];
    const float* bk    = (const float*)d_in[10];
    float* d_out = (float*)d_out_v;

    // streams + events (created once on the non-captured correctness call)
    static cudaStream_t s1 = nullptr, s2 = nullptr;
    static cudaEvent_t evFork = nullptr, evSide = nullptr, evKey = nullptr;
    if (s1 == nullptr) {
        cudaStreamCreateWithFlags(&s1, cudaStreamNonBlocking);
        cudaStreamCreateWithFlags(&s2, cudaStreamNonBlocking);
        cudaEventCreateWithFlags(&evFork, cudaEventDisableTiming);
        cudaEventCreateWithFlags(&evSide, cudaEventDisableTiming);
        cudaEventCreateWithFlags(&evKey,  cudaEventDisableTiming);
    }

#define SYM(var, sym) cudaGetSymbolAddress((void**)&var, sym)
    bf16 *queryh, *queryl, *keyh, *keyl, *Rh, *Rl;
    bf16 *wqh, *wql, *wkh, *wkl, *Ph, *Pl, *w1th, *w1tl, *w2th, *w2tl, *hh, *hl;
    bf16 *attnh, *attnl, *vth, *vtl;
    float *logits, *u, *v, *cvec, *dvec, *bb;
    SYM(queryh, g_queryh); SYM(queryl, g_queryl);
    SYM(keyh, g_keyh);     SYM(keyl, g_keyl);
    SYM(Rh, g_Rh); SYM(Rl, g_Rl);
    SYM(wqh, g_wqh); SYM(wql, g_wql);
    SYM(wkh, g_wkh); SYM(wkl, g_wkl);
    SYM(Ph, g_Ph); SYM(Pl, g_Pl);
    SYM(w1th, g_w1th); SYM(w1tl, g_w1tl);
    SYM(w2th, g_w2th); SYM(w2tl, g_w2tl);
    SYM(hh, g_hh); SYM(hl, g_hl);
    SYM(attnh, g_attnh); SYM(attnl, g_attnl);
    SYM(vth, g_vth); SYM(vtl, g_vtl);
    SYM(logits, g_logits);
    SYM(u, g_u); SYM(v, g_v); SYM(cvec, g_c); SYM(dvec, g_d); SYM(bb, g_bb);
#undef SYM

    const long long BSD = (long long)Bn * Sn * Dn;
    const long long BSS = (long long)Bn * Sn * Sn;

    float* out_ptr  = nullptr;
    float* attn_ptr = nullptr;
    if ((long long)out_size == BSD + BSS) { out_ptr = d_out; attn_ptr = d_out + BSD; }
    else if ((long long)out_size == BSS)  { attn_ptr = d_out; }
    else                                  { out_ptr = d_out; }

    const int BIGN = 1 << 30;
    float* attn_final = attn_ptr ? attn_ptr : logits;

    const long long sSD = (long long)Sn * Dn;
    const long long sSS = (long long)Sn * Sn;
    const long long sDS = (long long)Dn * Sn;
    const long long sSH = (long long)Sn * Hn;

    // ---- main: bias pre-vectors; fork ----
    dot_vec<<<1, 256>>>(bq, bk, bb, Dn);
    gemv_rows<<<Dn / 8, dim3(32, 8)>>>(wq, bk, u, Dn, nullptr);
    gemv_rows<<<Dn / 8, dim3(32, 8)>>>(wk, bq, v, Dn, nullptr);
    cudaEventRecord(evFork, 0);

    // ---- s1: query chain (query conv, transposes, h) ----
    cudaStreamWaitEvent(s1, evFork, 0);
    convert_split_dot<<<Mn, 256, 0, s1>>>(query, queryh, queryl, u, cvec, bb);
    transpose_split<<<dim3(Hn / 32, Dn / 32, 1), dim3(32, 8), 0, s1>>>(
        w1, w1th, w1tl, Dn, Hn, 0, 0);
    transpose_split<<<dim3(Sn / 32, 2, 1), dim3(32, 8), 0, s1>>>(
        w2, w2th, w2tl, Hn, Sn, 0, 0);
    transpose_split<<<dim3(Dn / 32, Sn / 32, Bn), dim3(32, 8), 0, s1>>>(
        value, vth, vtl, Sn, Dn, (long long)Sn * Dn, (long long)Sn * Dn);
    bf16_nt<false, true, true, false, true, true><<<dim3(1, Mn / 128, 1), 256, 0, s1>>>(
        queryh, queryl, w1th, w1tl, nullptr, nullptr, nullptr, nullptr,
        b1, nullptr, nullptr, nullptr, hh, hl,
        Hn, Dn, Dn, Dn, 0, 0, 0, 0, 0, 0, 0, Hn);
    cudaEventRecord(evSide, s1);

    // ---- s2: key convert (only feeds R; hides under wq/wk converts + P) ----
    cudaStreamWaitEvent(s2, evFork, 0);
    convert_split_dot<<<Mn, 256, 0, s2>>>(key, keyh, keyl, v, dvec, nullptr);
    cudaEventRecord(evKey, s2);

    // ---- main: wq/wk converts + P (concurrent with s1, s2) ----
    convert_split<<<(Dn * (Dn / 4) + 255) / 256, 256>>>(wq, wqh, wql, Dn * (Dn / 4));
    convert_split<<<(Dn * (Dn / 4) + 255) / 256, 256>>>(wk, wkh, wkl, Dn * (Dn / 4));
    bf16_nt<false, false, true, false, false, false><<<dim3(Dn / 128, Dn / 128, 1), 256>>>(
        wqh, wql, wkh, wkl, nullptr, nullptr, nullptr, nullptr,
        nullptr, nullptr, nullptr, nullptr, Ph, Pl,
        Dn, Dn, Dn, Dn, 0, 0, 0, 0, 0, 0, 0, BIGN);

    // ---- main: R = key @ P^T (needs keyh) ----
    cudaStreamWaitEvent(0, evKey, 0);
    bf16_nt<false, false, true, false, false, false><<<dim3(Dn / 128, Mn / 128, 1), 256>>>(
        keyh, keyl, Ph, Pl, nullptr, nullptr, nullptr, nullptr,
        nullptr, nullptr, nullptr, nullptr, Rh, Rl,
        Dn, Dn, Dn, Dn, 0, 0, 0, 0, 0, 0, 0, BIGN);

    // ---- join side chain, then logits / softmax / AV (single full launches) --
    cudaStreamWaitEvent(0, evSide, 0);

    bf16_nt<true, true, false, true, false, false><<<dim3(Sn / 128, Sn / 128, Bn), 256>>>(
        queryh, queryl, Rh, Rl, hh, hl, w2th, w2tl,
        b2, cvec, dvec, logits, nullptr, nullptr,
        Sn, Dn, Dn, Dn, Hn, Hn, Hn, sSD, sSD, sSS, sSH, BIGN);

    softmax_kernel<<<Bn * Sn, 256>>>(logits, attn_final, attnh, attnl);

    if (out_ptr) {
        bf16_nt<false, false, false, false, false, false><<<dim3(Dn / 128, Sn / 128, Bn), 256>>>(
            attnh, attnl, vth, vtl, nullptr, nullptr, nullptr, nullptr,
            nullptr, nullptr, nullptr, out_ptr, nullptr, nullptr,
            Dn, Sn, Sn, Sn, 0, 0, 0, sSS, sDS, sSD, 0, BIGN);
    }
}